// round 2
// baseline (speedup 1.0000x reference)
#include <cuda_runtime.h>
#include <cuda_bf16.h>
#include <math.h>
#include <stdint.h>

// Problem dims
#define Bv     16
#define Sv     2048
#define Hv     1024
#define NSPAN  64
#define NROW   (Bv * NSPAN)   // 1024
#define NCLS   4096

// ArcFace constants (double-evaluated, stored as float)
#define SCALE_F 30.0f
#define COS_M_F 0.8775825618903728f
#define SIN_M_F 0.479425538604203f
#define TH_F    (-0.8775825618903728f)
#define MM_F    0.2397127693021015f

// Scratch (static device memory; no allocations allowed)
__device__ __nv_bfloat16 g_emb[NROW * Hv];     // 2 MB
__device__ __nv_bfloat16 g_w[NCLS * Hv];       // 8 MB
__device__ float         g_cos[(size_t)NROW * NCLS]; // 16 MB
__device__ float         g_nll[NROW];

// ---------------------------------------------------------------------------
// block-wide sum over 256 threads
// ---------------------------------------------------------------------------
__device__ __forceinline__ float block_sum256(float v) {
    __shared__ float buf[8];
    #pragma unroll
    for (int o = 16; o; o >>= 1) v += __shfl_xor_sync(0xffffffffu, v, o);
    int t = threadIdx.x;
    if ((t & 31) == 0) buf[t >> 5] = v;
    __syncthreads();
    float r;
    if (t < 32) {
        float x = (t < 8) ? buf[t] : 0.0f;
        #pragma unroll
        for (int o = 4; o; o >>= 1) x += __shfl_xor_sync(0xffffffffu, x, o);
        if (t == 0) buf[0] = x;
    }
    __syncthreads();
    r = buf[0];
    __syncthreads();   // allow buf reuse on next call
    return r;
}

// ---------------------------------------------------------------------------
// Kernel 1: span mean + LayerNorm + L2 normalize -> bf16 emb [1024][1024]
// one block per (b, span) row; 256 threads, 4 columns each
// ---------------------------------------------------------------------------
__global__ void span_embed_kernel(const float* __restrict__ enc,
                                  const float* __restrict__ gamma,
                                  const float* __restrict__ beta,
                                  const int*   __restrict__ heads,
                                  const int*   __restrict__ tails) {
    const int row = blockIdx.x;          // 0..1023
    const int b   = row >> 6;            // /NSPAN
    const int t   = threadIdx.x;

    const int head = heads[row];
    const int tail = tails[row];
    const float inv_len = 1.0f / (float)(tail - head);

    const float* base = enc + (size_t)b * Sv * Hv;

    float acc[4] = {0.f, 0.f, 0.f, 0.f};
    for (int r = head; r < tail; ++r) {
        const float* p = base + (size_t)r * Hv;
        #pragma unroll
        for (int j = 0; j < 4; ++j) acc[j] += p[t + 256 * j];
    }
    #pragma unroll
    for (int j = 0; j < 4; ++j) acc[j] *= inv_len;

    // LayerNorm statistics over H=1024
    float s = 0.f, s2 = 0.f;
    #pragma unroll
    for (int j = 0; j < 4; ++j) { s += acc[j]; s2 += acc[j] * acc[j]; }
    const float mu  = block_sum256(s)  * (1.0f / Hv);
    const float ex2 = block_sum256(s2) * (1.0f / Hv);
    const float var = ex2 - mu * mu;
    const float rstd = rsqrtf(var + 1e-7f);

    float y[4]; float yn2 = 0.f;
    #pragma unroll
    for (int j = 0; j < 4; ++j) {
        const int c = t + 256 * j;
        y[j] = (acc[j] - mu) * rstd * gamma[c] + beta[c];
        yn2 += y[j] * y[j];
    }
    const float nrm = sqrtf(block_sum256(yn2));
    const float inv = 1.0f / fmaxf(nrm, 1e-12f);

    __nv_bfloat16* out = g_emb + (size_t)row * Hv;
    #pragma unroll
    for (int j = 0; j < 4; ++j) {
        const int c = t + 256 * j;
        out[c] = __float2bfloat16(y[j] * inv);
    }
}

// ---------------------------------------------------------------------------
// Kernel 2: L2-normalize arc_weight rows -> bf16 W [4096][1024]
// ---------------------------------------------------------------------------
__global__ void wnorm_kernel(const float* __restrict__ w) {
    const int row = blockIdx.x;          // 0..4095
    const int t   = threadIdx.x;
    const float* p = w + (size_t)row * Hv;

    float v[4]; float s2 = 0.f;
    #pragma unroll
    for (int j = 0; j < 4; ++j) { v[j] = p[t + 256 * j]; s2 += v[j] * v[j]; }
    const float nrm = sqrtf(block_sum256(s2));
    const float inv = 1.0f / fmaxf(nrm, 1e-12f);

    __nv_bfloat16* out = g_w + (size_t)row * Hv;
    #pragma unroll
    for (int j = 0; j < 4; ++j) out[t + 256 * j] = __float2bfloat16(v[j] * inv);
}

// ---------------------------------------------------------------------------
// Kernel 3: cosine = emb @ W^T  [1024 x 4096], K=1024, bf16 mma.sync
// block tile 128x128, BK=32, 8 warps in 4(m) x 2(n), warp tile 32x64
// ---------------------------------------------------------------------------
#define BM 128
#define BN 128
#define BK 32
#define LDS_STRIDE 40   // BK + 8 bf16 pad -> 20-word row stride, conflict-free

__device__ __forceinline__ void mma16816(float c[4], const uint32_t a[4],
                                         const uint32_t b[2]) {
    asm volatile(
        "mma.sync.aligned.m16n8k16.row.col.f32.bf16.bf16.f32 "
        "{%0,%1,%2,%3}, {%4,%5,%6,%7}, {%8,%9}, {%0,%1,%2,%3};\n"
        : "+f"(c[0]), "+f"(c[1]), "+f"(c[2]), "+f"(c[3])
        : "r"(a[0]), "r"(a[1]), "r"(a[2]), "r"(a[3]), "r"(b[0]), "r"(b[1]));
}

__global__ void __launch_bounds__(256) gemm_kernel() {
    __shared__ __nv_bfloat16 sA[BM * LDS_STRIDE];
    __shared__ __nv_bfloat16 sB[BN * LDS_STRIDE];

    const int bm = blockIdx.y * BM;
    const int bn = blockIdx.x * BN;
    const int tid  = threadIdx.x;
    const int warp = tid >> 5;
    const int lane = tid & 31;
    const int wm = (warp & 3) * 32;   // warp m-offset in tile
    const int wn = (warp >> 2) * 64;  // warp n-offset in tile
    const int g   = lane >> 2;        // groupID
    const int tig = lane & 3;         // thread-in-group

    float acc[2][8][4];
    #pragma unroll
    for (int mt = 0; mt < 2; ++mt)
        #pragma unroll
        for (int nt = 0; nt < 8; ++nt)
            #pragma unroll
            for (int i = 0; i < 4; ++i) acc[mt][nt][i] = 0.f;

    for (int k0 = 0; k0 < Hv; k0 += BK) {
        // stage tiles: 128 rows x 32 bf16 each = 512 uint4; 2 per thread
        #pragma unroll
        for (int i = 0; i < 2; ++i) {
            const int idx = tid + 256 * i;
            const int r = idx >> 2;
            const int c = (idx & 3) * 8;
            const uint4 va = *(const uint4*)(&g_emb[(size_t)(bm + r) * Hv + k0 + c]);
            *(uint4*)(&sA[r * LDS_STRIDE + c]) = va;
            const uint4 vb = *(const uint4*)(&g_w[(size_t)(bn + r) * Hv + k0 + c]);
            *(uint4*)(&sB[r * LDS_STRIDE + c]) = vb;
        }
        __syncthreads();

        #pragma unroll
        for (int kk = 0; kk < BK; kk += 16) {
            uint32_t afr[2][4];
            #pragma unroll
            for (int mt = 0; mt < 2; ++mt) {
                const int rb = wm + mt * 16;
                afr[mt][0] = *(const uint32_t*)&sA[(rb + g)     * LDS_STRIDE + kk     + 2 * tig];
                afr[mt][1] = *(const uint32_t*)&sA[(rb + g + 8) * LDS_STRIDE + kk     + 2 * tig];
                afr[mt][2] = *(const uint32_t*)&sA[(rb + g)     * LDS_STRIDE + kk + 8 + 2 * tig];
                afr[mt][3] = *(const uint32_t*)&sA[(rb + g + 8) * LDS_STRIDE + kk + 8 + 2 * tig];
            }
            uint32_t bfr[8][2];
            #pragma unroll
            for (int nt = 0; nt < 8; ++nt) {
                const int nb = wn + nt * 8;
                bfr[nt][0] = *(const uint32_t*)&sB[(nb + g) * LDS_STRIDE + kk     + 2 * tig];
                bfr[nt][1] = *(const uint32_t*)&sB[(nb + g) * LDS_STRIDE + kk + 8 + 2 * tig];
            }
            #pragma unroll
            for (int mt = 0; mt < 2; ++mt)
                #pragma unroll
                for (int nt = 0; nt < 8; ++nt)
                    mma16816(acc[mt][nt], afr[mt], bfr[nt]);
        }
        __syncthreads();
    }

    // epilogue: write fp32 cosine
    #pragma unroll
    for (int mt = 0; mt < 2; ++mt) {
        const int r0 = bm + wm + mt * 16 + g;
        #pragma unroll
        for (int nt = 0; nt < 8; ++nt) {
            const int c0 = bn + wn + nt * 8 + 2 * tig;
            float* p0 = &g_cos[(size_t)r0 * NCLS + c0];
            p0[0] = acc[mt][nt][0];
            p0[1] = acc[mt][nt][1];
            float* p1 = &g_cos[(size_t)(r0 + 8) * NCLS + c0];
            p1[0] = acc[mt][nt][2];
            p1[1] = acc[mt][nt][3];
        }
    }
}

// ---------------------------------------------------------------------------
// Kernel 4: per-row ArcFace margin + cross-entropy (fixed shift = SCALE)
// logits <= SCALE always, so shift by SCALE is exact-safe without a max pass.
// ---------------------------------------------------------------------------
__global__ void ce_kernel(const int* __restrict__ labels) {
    const int row = blockIdx.x;      // 0..1023
    const int t   = threadIdx.x;     // 256
    const int lab = labels[row];
    const float* cr = g_cos + (size_t)row * NCLS;

    float se = 0.f;
    float llab = 0.f;
    for (int c = t; c < NCLS; c += 256) {
        const float cs = cr[c];
        float logit;
        if (c == lab) {
            const float sine = sqrtf(fmaxf(1.0f - cs * cs, 0.0f));
            float phi = cs * COS_M_F - sine * SIN_M_F;
            phi = (cs > TH_F) ? phi : (cs - MM_F);
            logit = phi * SCALE_F;
            llab = logit;
        } else {
            logit = cs * SCALE_F;
        }
        se += __expf(logit - SCALE_F);
    }
    const float se_tot   = block_sum256(se);
    const float llab_tot = block_sum256(llab);   // exactly one nonzero contributor
    if (t == 0) g_nll[row] = (SCALE_F + logf(se_tot)) - llab_tot;
}

// ---------------------------------------------------------------------------
// Kernel 5: mean of nll -> out[0]
// ---------------------------------------------------------------------------
__global__ void mean_kernel(float* __restrict__ out) {
    const int t = threadIdx.x;
    float s = 0.f;
    for (int i = t; i < NROW; i += 256) s += g_nll[i];
    const float tot = block_sum256(s);
    if (t == 0) out[0] = tot * (1.0f / NROW);
}

// ---------------------------------------------------------------------------
// launch
// inputs: 0 encoder_layer f32 [16,2048,1024], 1 ln_gamma f32 [1024],
//         2 ln_beta f32 [1024], 3 arc_weight f32 [4096,1024],
//         4 span_head_idxs i32 [16,64], 5 span_tail_idxs i32 [16,64],
//         6 labels i32 [16,64]; output: f32 scalar
// ---------------------------------------------------------------------------
extern "C" void kernel_launch(void* const* d_in, const int* in_sizes, int n_in,
                              void* d_out, int out_size) {
    const float* enc   = (const float*)d_in[0];
    const float* gamma = (const float*)d_in[1];
    const float* beta  = (const float*)d_in[2];
    const float* w     = (const float*)d_in[3];
    const int* heads   = (const int*)d_in[4];
    const int* tails   = (const int*)d_in[5];
    const int* labels  = (const int*)d_in[6];
    float* out = (float*)d_out;

    span_embed_kernel<<<NROW, 256>>>(enc, gamma, beta, heads, tails);
    wnorm_kernel<<<NCLS, 256>>>(w);
    dim3 ggrid(NCLS / BN, NROW / BM);   // (32, 8)
    gemm_kernel<<<ggrid, 256>>>();
    ce_kernel<<<NROW, 256>>>(labels);
    mean_kernel<<<1, 256>>>(out);
}

// round 3
// speedup vs baseline: 1.2582x; 1.2582x over previous
#include <cuda_runtime.h>
#include <cuda_bf16.h>
#include <math.h>
#include <stdint.h>

// Problem dims
#define Bv     16
#define Sv     2048
#define Hv     1024
#define NSPAN  64
#define NROW   (Bv * NSPAN)   // 1024
#define NCLS   4096

// ArcFace constants
#define SCALE_F 30.0f
#define COS_M_F 0.8775825618903728f
#define SIN_M_F 0.479425538604203f
#define TH_F    (-0.8775825618903728f)
#define MM_F    0.2397127693021015f

// Scratch (static device memory)
__device__ __nv_bfloat16 g_emb[NROW * Hv];     // 2 MB
__device__ __nv_bfloat16 g_w[NCLS * Hv];       // 8 MB
__device__ float         g_sumexp[NROW];
__device__ float         g_llab[NROW];

// ---------------------------------------------------------------------------
__device__ __forceinline__ float block_sum256(float v) {
    __shared__ float buf[8];
    #pragma unroll
    for (int o = 16; o; o >>= 1) v += __shfl_xor_sync(0xffffffffu, v, o);
    int t = threadIdx.x;
    if ((t & 31) == 0) buf[t >> 5] = v;
    __syncthreads();
    float r;
    if (t < 32) {
        float x = (t < 8) ? buf[t] : 0.0f;
        #pragma unroll
        for (int o = 4; o; o >>= 1) x += __shfl_xor_sync(0xffffffffu, x, o);
        if (t == 0) buf[0] = x;
    }
    __syncthreads();
    r = buf[0];
    __syncthreads();
    return r;
}

// ---------------------------------------------------------------------------
// Kernel 0: zero the per-row softmax accumulators
// ---------------------------------------------------------------------------
__global__ void zero_kernel() {
    const int i = blockIdx.x * blockDim.x + threadIdx.x;
    if (i < NROW) g_sumexp[i] = 0.0f;
}

// ---------------------------------------------------------------------------
// Kernel 1: span mean + LayerNorm + L2 normalize -> bf16 emb [1024][1024]
// one block per row; 256 threads, float4 columns, 2-row unroll
// ---------------------------------------------------------------------------
__global__ void span_embed_kernel(const float* __restrict__ enc,
                                  const float* __restrict__ gamma,
                                  const float* __restrict__ beta,
                                  const int*   __restrict__ heads,
                                  const int*   __restrict__ tails) {
    const int row = blockIdx.x;
    const int b   = row >> 6;
    const int t   = threadIdx.x;

    const int head = heads[row];
    const int tail = tails[row];
    const float inv_len = 1.0f / (float)(tail - head);

    const float4* base = (const float4*)(enc + (size_t)b * Sv * Hv);
    const int RW = Hv / 4;   // 256 float4 per row

    float4 a = make_float4(0.f, 0.f, 0.f, 0.f);
    int r = head;
    for (; r + 1 < tail; r += 2) {
        const float4 x = base[(size_t)r * RW + t];
        const float4 y = base[(size_t)(r + 1) * RW + t];
        a.x += x.x + y.x; a.y += x.y + y.y;
        a.z += x.z + y.z; a.w += x.w + y.w;
    }
    if (r < tail) {
        const float4 x = base[(size_t)r * RW + t];
        a.x += x.x; a.y += x.y; a.z += x.z; a.w += x.w;
    }
    a.x *= inv_len; a.y *= inv_len; a.z *= inv_len; a.w *= inv_len;

    const float s  = a.x + a.y + a.z + a.w;
    const float s2 = a.x * a.x + a.y * a.y + a.z * a.z + a.w * a.w;
    const float mu   = block_sum256(s)  * (1.0f / Hv);
    const float ex2  = block_sum256(s2) * (1.0f / Hv);
    const float rstd = rsqrtf(ex2 - mu * mu + 1e-7f);

    const float4 gm = ((const float4*)gamma)[t];
    const float4 bt = ((const float4*)beta)[t];
    float y0 = (a.x - mu) * rstd * gm.x + bt.x;
    float y1 = (a.y - mu) * rstd * gm.y + bt.y;
    float y2 = (a.z - mu) * rstd * gm.z + bt.z;
    float y3 = (a.w - mu) * rstd * gm.w + bt.w;

    const float yn2 = y0 * y0 + y1 * y1 + y2 * y2 + y3 * y3;
    const float nrm = sqrtf(block_sum256(yn2));
    const float inv = 1.0f / fmaxf(nrm, 1e-12f);

    __nv_bfloat162* o2 = (__nv_bfloat162*)(g_emb + (size_t)row * Hv);
    o2[2 * t]     = __floats2bfloat162_rn(y0 * inv, y1 * inv);
    o2[2 * t + 1] = __floats2bfloat162_rn(y2 * inv, y3 * inv);
}

// ---------------------------------------------------------------------------
// Kernel 2: L2-normalize arc_weight rows -> bf16 W [4096][1024]
// ---------------------------------------------------------------------------
__global__ void wnorm_kernel(const float* __restrict__ w) {
    const int row = blockIdx.x;
    const int t   = threadIdx.x;
    const float4 v = ((const float4*)(w + (size_t)row * Hv))[t];

    const float s2 = v.x * v.x + v.y * v.y + v.z * v.z + v.w * v.w;
    const float nrm = sqrtf(block_sum256(s2));
    const float inv = 1.0f / fmaxf(nrm, 1e-12f);

    __nv_bfloat162* o2 = (__nv_bfloat162*)(g_w + (size_t)row * Hv);
    o2[2 * t]     = __floats2bfloat162_rn(v.x * inv, v.y * inv);
    o2[2 * t + 1] = __floats2bfloat162_rn(v.z * inv, v.w * inv);
}

// ---------------------------------------------------------------------------
// Kernel 3: cosine GEMM [1024 x 4096] K=1024 (bf16 mma.sync) fused with
// ArcFace margin + partial softmax reduction.
// block tile 128x128, BK=32 double-buffered cp.async; 8 warps 4(m)x2(n)
// ---------------------------------------------------------------------------
#define BM 128
#define BN 128
#define BK 32
#define LDS_STRIDE 40   // BK + 8 pad bf16 -> conflict-free

__device__ __forceinline__ void cp_async16(void* smem, const void* gmem) {
    uint32_t s = (uint32_t)__cvta_generic_to_shared(smem);
    asm volatile("cp.async.cg.shared.global [%0], [%1], 16;\n" :: "r"(s), "l"(gmem));
}
#define CP_COMMIT asm volatile("cp.async.commit_group;\n" ::: "memory")
#define CP_WAIT0  asm volatile("cp.async.wait_group 0;\n" ::: "memory")

__device__ __forceinline__ void mma16816(float c[4], const uint32_t a[4],
                                         const uint32_t b[2]) {
    asm volatile(
        "mma.sync.aligned.m16n8k16.row.col.f32.bf16.bf16.f32 "
        "{%0,%1,%2,%3}, {%4,%5,%6,%7}, {%8,%9}, {%0,%1,%2,%3};\n"
        : "+f"(c[0]), "+f"(c[1]), "+f"(c[2]), "+f"(c[3])
        : "r"(a[0]), "r"(a[1]), "r"(a[2]), "r"(a[3]), "r"(b[0]), "r"(b[1]));
}

__global__ void __launch_bounds__(256) gemm_fused_kernel(const int* __restrict__ labels) {
    __shared__ __nv_bfloat16 sA[2][BM * LDS_STRIDE];
    __shared__ __nv_bfloat16 sB[2][BN * LDS_STRIDE];
    __shared__ float rs[BM];

    const int bm = blockIdx.y * BM;
    const int bn = blockIdx.x * BN;
    const int tid  = threadIdx.x;
    const int warp = tid >> 5;
    const int lane = tid & 31;
    const int wm  = (warp & 3) * 32;
    const int wn  = (warp >> 2) * 64;
    const int g   = lane >> 2;
    const int tig = lane & 3;

    // stage indices (computed once)
    const int r0 = tid >> 2;            // 0..63
    const int c0s = (tid & 3) * 8;      // 0,8,16,24
    const int r1 = r0 + 64;

    float acc[2][8][4];
    #pragma unroll
    for (int mt = 0; mt < 2; ++mt)
        #pragma unroll
        for (int nt = 0; nt < 8; ++nt)
            #pragma unroll
            for (int i = 0; i < 4; ++i) acc[mt][nt][i] = 0.f;

    // prologue: stage k-tile 0 into buffer 0
    {
        cp_async16(&sA[0][r0 * LDS_STRIDE + c0s], &g_emb[(size_t)(bm + r0) * Hv + c0s]);
        cp_async16(&sA[0][r1 * LDS_STRIDE + c0s], &g_emb[(size_t)(bm + r1) * Hv + c0s]);
        cp_async16(&sB[0][r0 * LDS_STRIDE + c0s], &g_w[(size_t)(bn + r0) * Hv + c0s]);
        cp_async16(&sB[0][r1 * LDS_STRIDE + c0s], &g_w[(size_t)(bn + r1) * Hv + c0s]);
        CP_COMMIT;
    }

    const int KT = Hv / BK;   // 32
    for (int kt = 0; kt < KT; ++kt) {
        CP_WAIT0;
        __syncthreads();
        if (kt + 1 < KT) {
            const int nb = (kt + 1) & 1;
            const int k0 = (kt + 1) * BK;
            cp_async16(&sA[nb][r0 * LDS_STRIDE + c0s], &g_emb[(size_t)(bm + r0) * Hv + k0 + c0s]);
            cp_async16(&sA[nb][r1 * LDS_STRIDE + c0s], &g_emb[(size_t)(bm + r1) * Hv + k0 + c0s]);
            cp_async16(&sB[nb][r0 * LDS_STRIDE + c0s], &g_w[(size_t)(bn + r0) * Hv + k0 + c0s]);
            cp_async16(&sB[nb][r1 * LDS_STRIDE + c0s], &g_w[(size_t)(bn + r1) * Hv + k0 + c0s]);
            CP_COMMIT;
        }
        const __nv_bfloat16* A = sA[kt & 1];
        const __nv_bfloat16* B = sB[kt & 1];

        #pragma unroll
        for (int kk = 0; kk < BK; kk += 16) {
            uint32_t afr[2][4];
            #pragma unroll
            for (int mt = 0; mt < 2; ++mt) {
                const int rb = wm + mt * 16;
                afr[mt][0] = *(const uint32_t*)&A[(rb + g)     * LDS_STRIDE + kk     + 2 * tig];
                afr[mt][1] = *(const uint32_t*)&A[(rb + g + 8) * LDS_STRIDE + kk     + 2 * tig];
                afr[mt][2] = *(const uint32_t*)&A[(rb + g)     * LDS_STRIDE + kk + 8 + 2 * tig];
                afr[mt][3] = *(const uint32_t*)&A[(rb + g + 8) * LDS_STRIDE + kk + 8 + 2 * tig];
            }
            uint32_t bfr[8][2];
            #pragma unroll
            for (int nt = 0; nt < 8; ++nt) {
                const int nb = wn + nt * 8;
                bfr[nt][0] = *(const uint32_t*)&B[(nb + g) * LDS_STRIDE + kk     + 2 * tig];
                bfr[nt][1] = *(const uint32_t*)&B[(nb + g) * LDS_STRIDE + kk + 8 + 2 * tig];
            }
            #pragma unroll
            for (int mt = 0; mt < 2; ++mt)
                #pragma unroll
                for (int nt = 0; nt < 8; ++nt)
                    mma16816(acc[mt][nt], afr[mt], bfr[nt]);
        }
        __syncthreads();
    }

    // ---------------- fused ArcFace + partial softmax epilogue ----------------
    if (tid < BM) rs[tid] = 0.0f;
    __syncthreads();

    #pragma unroll
    for (int mt = 0; mt < 2; ++mt) {
        const int rl1 = wm + mt * 16 + g;    // block-local rows
        const int rl2 = rl1 + 8;
        const int gr1 = bm + rl1;
        const int gr2 = bm + rl2;
        const int lab1 = labels[gr1];
        const int lab2 = labels[gr2];

        float s1 = 0.f, s2 = 0.f;
        #pragma unroll
        for (int nt = 0; nt < 8; ++nt) {
            const int c0 = bn + wn + nt * 8 + 2 * tig;
            #pragma unroll
            for (int e = 0; e < 2; ++e) {
                const int c = c0 + e;
                // row 1
                {
                    const float cs = acc[mt][nt][e];
                    float l = cs * SCALE_F;
                    if (c == lab1) {
                        const float sine = sqrtf(fmaxf(1.0f - cs * cs, 0.0f));
                        float phi = cs * COS_M_F - sine * SIN_M_F;
                        phi = (cs > TH_F) ? phi : (cs - MM_F);
                        l = phi * SCALE_F;
                        g_llab[gr1] = l;
                    }
                    s1 += __expf(l - SCALE_F);
                }
                // row 2
                {
                    const float cs = acc[mt][nt][2 + e];
                    float l = cs * SCALE_F;
                    if (c == lab2) {
                        const float sine = sqrtf(fmaxf(1.0f - cs * cs, 0.0f));
                        float phi = cs * COS_M_F - sine * SIN_M_F;
                        phi = (cs > TH_F) ? phi : (cs - MM_F);
                        l = phi * SCALE_F;
                        g_llab[gr2] = l;
                    }
                    s2 += __expf(l - SCALE_F);
                }
            }
        }
        // reduce over the 4 tig lanes (lane = g*4 + tig)
        #pragma unroll
        for (int o = 1; o <= 2; o <<= 1) {
            s1 += __shfl_xor_sync(0xffffffffu, s1, o);
            s2 += __shfl_xor_sync(0xffffffffu, s2, o);
        }
        if (tig == 0) {
            atomicAdd(&rs[rl1], s1);
            atomicAdd(&rs[rl2], s2);
        }
    }
    __syncthreads();
    if (tid < BM) atomicAdd(&g_sumexp[bm + tid], rs[tid]);
}

// ---------------------------------------------------------------------------
// Kernel 4: nll per row + mean -> out[0]
// ---------------------------------------------------------------------------
__global__ void final_kernel(float* __restrict__ out) {
    const int t = threadIdx.x;
    float s = 0.f;
    for (int i = t; i < NROW; i += 256)
        s += (SCALE_F + logf(g_sumexp[i])) - g_llab[i];
    const float tot = block_sum256(s);
    if (t == 0) out[0] = tot * (1.0f / NROW);
}

// ---------------------------------------------------------------------------
extern "C" void kernel_launch(void* const* d_in, const int* in_sizes, int n_in,
                              void* d_out, int out_size) {
    const float* enc   = (const float*)d_in[0];
    const float* gamma = (const float*)d_in[1];
    const float* beta  = (const float*)d_in[2];
    const float* w     = (const float*)d_in[3];
    const int* heads   = (const int*)d_in[4];
    const int* tails   = (const int*)d_in[5];
    const int* labels  = (const int*)d_in[6];
    float* out = (float*)d_out;

    zero_kernel<<<4, 256>>>();
    span_embed_kernel<<<NROW, 256>>>(enc, gamma, beta, heads, tails);
    wnorm_kernel<<<NCLS, 256>>>(w);
    dim3 ggrid(NCLS / BN, NROW / BM);   // (32, 8)
    gemm_fused_kernel<<<ggrid, 256>>>(labels);
    final_kernel<<<1, 256>>>(out);
}